// round 1
// baseline (speedup 1.0000x reference)
#include <cuda_runtime.h>
#include <cstdint>
#include <cstddef>

// Problem constants
#define RH 512        // hidden size H
#define RB 64         // batch B
#define RS 2048       // seq len S
#define RI 512        // input size I

// ---------------------------------------------------------------------------
// Phase 1: x_proj GEMM  out[(s*B+b)*H + h] = inputs[b,s,:]·w_ih[h,:] + bih+bhh
// Tile: BM=64 (one s, all 64 b), BN=64, BK=16, 256 threads, 4x4 per thread.
// ---------------------------------------------------------------------------
#define BM 64
#define BN 64
#define BK 16

__global__ void __launch_bounds__(256)
rnn_xproj(const float* __restrict__ A,    // inputs [B,S,I]
          const float* __restrict__ Wih,  // [H,I]
          const float* __restrict__ bih,
          const float* __restrict__ bhh,
          float* __restrict__ out)
{
    __shared__ float As[BK][BM + 4];   // pitch 68 floats (16B-aligned rows)
    __shared__ float Ws[BK][BN + 4];

    const int tid = threadIdx.x;
    const int s  = blockIdx.y;            // BM==B, so one tile == one timestep
    const int h0 = blockIdx.x * BN;
    const int r0 = s * RB;                // output row base (s*B + b)

    const int tm0 = (tid >> 4) << 2;      // 0..60
    const int tn0 = (tid & 15) << 2;      // 0..60

    const int lr  = tid >> 2;             // load row 0..63 (b for A, h for W)
    const int lk4 = (tid & 3) << 2;       // 0,4,8,12

    const float* Arow = A + ((size_t)lr * RS + s) * RI;
    const float* Wrow = Wih + (size_t)(h0 + lr) * RI;

    float c[4][4] = {};

    for (int k0 = 0; k0 < RI; k0 += BK) {
        float4 av = *reinterpret_cast<const float4*>(Arow + k0 + lk4);
        float4 wv = *reinterpret_cast<const float4*>(Wrow + k0 + lk4);
        As[lk4 + 0][lr] = av.x;
        As[lk4 + 1][lr] = av.y;
        As[lk4 + 2][lr] = av.z;
        As[lk4 + 3][lr] = av.w;
        Ws[lk4 + 0][lr] = wv.x;
        Ws[lk4 + 1][lr] = wv.y;
        Ws[lk4 + 2][lr] = wv.z;
        Ws[lk4 + 3][lr] = wv.w;
        __syncthreads();
        #pragma unroll
        for (int kk = 0; kk < BK; kk++) {
            float4 a = *reinterpret_cast<const float4*>(&As[kk][tm0]);
            float4 b = *reinterpret_cast<const float4*>(&Ws[kk][tn0]);
            c[0][0] = fmaf(a.x, b.x, c[0][0]);
            c[0][1] = fmaf(a.x, b.y, c[0][1]);
            c[0][2] = fmaf(a.x, b.z, c[0][2]);
            c[0][3] = fmaf(a.x, b.w, c[0][3]);
            c[1][0] = fmaf(a.y, b.x, c[1][0]);
            c[1][1] = fmaf(a.y, b.y, c[1][1]);
            c[1][2] = fmaf(a.y, b.z, c[1][2]);
            c[1][3] = fmaf(a.y, b.w, c[1][3]);
            c[2][0] = fmaf(a.z, b.x, c[2][0]);
            c[2][1] = fmaf(a.z, b.y, c[2][1]);
            c[2][2] = fmaf(a.z, b.z, c[2][2]);
            c[2][3] = fmaf(a.z, b.w, c[2][3]);
            c[3][0] = fmaf(a.w, b.x, c[3][0]);
            c[3][1] = fmaf(a.w, b.y, c[3][1]);
            c[3][2] = fmaf(a.w, b.z, c[3][2]);
            c[3][3] = fmaf(a.w, b.w, c[3][3]);
        }
        __syncthreads();
    }

    const int hbase = h0 + tn0;
    float bs0 = bih[hbase + 0] + bhh[hbase + 0];
    float bs1 = bih[hbase + 1] + bhh[hbase + 1];
    float bs2 = bih[hbase + 2] + bhh[hbase + 2];
    float bs3 = bih[hbase + 3] + bhh[hbase + 3];
    #pragma unroll
    for (int im = 0; im < 4; im++) {
        int r = r0 + tm0 + im;
        float4 o;
        o.x = c[im][0] + bs0;
        o.y = c[im][1] + bs1;
        o.z = c[im][2] + bs2;
        o.w = c[im][3] + bs3;
        *reinterpret_cast<float4*>(&out[(size_t)r * RH + hbase]) = o;
    }
}

// ---------------------------------------------------------------------------
// Phase 2: recurrence. 16 clusters x 8 CTAs, 512 threads/CTA.
// CTA (rank r in cluster) owns W_hh rows [r*64, r*64+64) in SMEM.
// Cluster cl owns batches [cl*4, cl*4+4); h replicated per CTA, double-buffered.
// Per step: each warp computes 4 j's x 4 b's; lanes split k into 8 chunks of 64;
// shfl-reduce over kg lanes; broadcast new h slice to all 8 CTAs via DSMEM;
// one barrier.cluster per step.
// ---------------------------------------------------------------------------
#define CSZ 8
#define W_F4    8704            // 512 (j,kg) blocks * 17 float4
#define HBUF_F4 544             // 32 (b,kg) blocks * 17 float4
#define SMEM_BYTES ((W_F4 + 2 * HBUF_F4) * 16)   // 156,672 B

__device__ __forceinline__ uint32_t smem_u32(const void* p) {
    return (uint32_t)__cvta_generic_to_shared(p);
}
__device__ __forceinline__ uint32_t mapa_u32(uint32_t addr, uint32_t rank) {
    uint32_t r;
    asm("mapa.shared::cluster.u32 %0, %1, %2;" : "=r"(r) : "r"(addr), "r"(rank));
    return r;
}
__device__ __forceinline__ void st_cluster_f32(uint32_t addr, float v) {
    asm volatile("st.shared::cluster.f32 [%0], %1;" :: "r"(addr), "f"(v) : "memory");
}

__global__ void __cluster_dims__(CSZ, 1, 1) __launch_bounds__(512, 1)
rnn_recur(const float* __restrict__ w_hh,
          const float* __restrict__ state,
          float* __restrict__ out,
          int has_tail)
{
    extern __shared__ float4 sm4[];
    float4* Wv = sm4;
    float4* Hv = sm4 + W_F4;

    const int tid = threadIdx.x;
    const int w = tid >> 5;
    const int l = tid & 31;
    uint32_t rank;
    asm("mov.u32 %0, %%cluster_ctarank;" : "=r"(rank));
    const int cl = blockIdx.x >> 3;
    const int j0 = (int)rank * 64;
    const int b0 = cl * 4;

    // Load W_hh slice: 64 rows x 512 cols, padded (17-f4 block) layout
    for (int v = tid; v < 64 * 128; v += 512) {
        int j  = v >> 7;
        int kv = v & 127;
        float4 x = __ldg(reinterpret_cast<const float4*>(w_hh) + ((size_t)(j0 + j) << 7) + kv);
        Wv[((j << 3) + (kv >> 4)) * 17 + (kv & 15)] = x;
    }
    // Load initial state into buf0
    for (int v = tid; v < 4 * 128; v += 512) {
        int b  = v >> 7;
        int kv = v & 127;
        float4 x = __ldg(reinterpret_cast<const float4*>(state) + ((size_t)(b0 + b) << 7) + kv);
        Hv[((b << 3) + (kv >> 4)) * 17 + (kv & 15)] = x;
    }
    __syncthreads();

    const int jj = l & 3;
    const int kg = l >> 2;                 // k-chunk 0..7 (64 k each)
    const int j_local = (w << 2) + jj;     // 0..63
    const bool act = (l < 16);
    const int ob = l >> 2;                 // output batch for active lanes

    const float4* Wp = Wv + ((j_local << 3) + kg) * 17;
    const float4* Hb = Hv + kg * 17;

    const size_t row_stride = (size_t)RB * RH;
    const size_t oidx = (size_t)(b0 + ob) * RH + (size_t)(j0 + j_local);

    // Remote slot addresses for broadcasting this lane's output value
    const int kglob = j0 + j_local;
    const int slot_f4 = W_F4 + ((ob << 3) + (kglob >> 6)) * 17 + ((kglob >> 2) & 15);
    const uint32_t slot_addr = smem_u32(sm4) + (uint32_t)slot_f4 * 16u + (uint32_t)(kglob & 3) * 4u;
    uint32_t rem[CSZ];
    #pragma unroll
    for (int c = 0; c < CSZ; c++) rem[c] = mapa_u32(slot_addr, (uint32_t)c);
    const uint32_t bufoff = HBUF_F4 * 16u;

    float xp_cur = 0.f;
    if (act) xp_cur = __ldg(out + oidx);

    int buf = 0;
    for (int s = 0; s < RS; ++s) {
        float xp_next = 0.f;
        if (act && (s + 1 < RS))
            xp_next = __ldg(out + oidx + (size_t)(s + 1) * row_stride);

        const float4* Hp = Hb + buf * (32 * 17);
        float p0 = 0.f, p1 = 0.f, p2 = 0.f, p3 = 0.f;
        float q0 = 0.f, q1 = 0.f, q2 = 0.f, q3 = 0.f;
        #pragma unroll
        for (int i = 0; i < 16; ++i) {
            float4 wv = Wp[i];
            float4 h0 = Hp[i];
            float4 h1 = Hp[8 * 17 + i];
            float4 h2 = Hp[16 * 17 + i];
            float4 h3 = Hp[24 * 17 + i];
            p0 = fmaf(wv.x, h0.x, p0); q0 = fmaf(wv.y, h0.y, q0);
            p0 = fmaf(wv.z, h0.z, p0); q0 = fmaf(wv.w, h0.w, q0);
            p1 = fmaf(wv.x, h1.x, p1); q1 = fmaf(wv.y, h1.y, q1);
            p1 = fmaf(wv.z, h1.z, p1); q1 = fmaf(wv.w, h1.w, q1);
            p2 = fmaf(wv.x, h2.x, p2); q2 = fmaf(wv.y, h2.y, q2);
            p2 = fmaf(wv.z, h2.z, p2); q2 = fmaf(wv.w, h2.w, q2);
            p3 = fmaf(wv.x, h3.x, p3); q3 = fmaf(wv.y, h3.y, q3);
            p3 = fmaf(wv.z, h3.z, p3); q3 = fmaf(wv.w, h3.w, q3);
        }
        float a0 = p0 + q0, a1 = p1 + q1, a2 = p2 + q2, a3 = p3 + q3;
        #pragma unroll
        for (int off = 4; off < 32; off <<= 1) {
            a0 += __shfl_xor_sync(0xffffffffu, a0, off);
            a1 += __shfl_xor_sync(0xffffffffu, a1, off);
            a2 += __shfl_xor_sync(0xffffffffu, a2, off);
            a3 += __shfl_xor_sync(0xffffffffu, a3, off);
        }

        if (act) {
            float acc = (ob == 0) ? a0 : ((ob == 1) ? a1 : ((ob == 2) ? a2 : a3));
            float y = tanhf(xp_cur + acc);
            out[oidx + (size_t)s * row_stride] = y;            // hidden_seq (overwrites xp slot)
            if (has_tail && (s == RS - 1))
                out[(size_t)RS * RB * RH + (size_t)kglob * RB + (size_t)(b0 + ob)] = y;
            uint32_t woff = buf ? 0u : bufoff;                 // write the other buffer
            #pragma unroll
            for (int c = 0; c < CSZ; c++) st_cluster_f32(rem[c] + woff, y);
        }

        asm volatile("barrier.cluster.arrive.aligned;" ::: "memory");
        asm volatile("barrier.cluster.wait.aligned;"   ::: "memory");

        buf ^= 1;
        xp_cur = xp_next;
    }
}

// ---------------------------------------------------------------------------
// Launch
// ---------------------------------------------------------------------------
extern "C" void kernel_launch(void* const* d_in, const int* in_sizes, int n_in,
                              void* d_out, int out_size)
{
    const float* inputs = (const float*)d_in[0];   // [B,S,I]
    const float* state  = (const float*)d_in[1];   // [B,H]
    const float* w_ih   = (const float*)d_in[2];   // [H,I]
    const float* b_ih   = (const float*)d_in[3];   // [H,1]
    const float* w_hh   = (const float*)d_in[4];   // [H,H]
    const float* b_hh   = (const float*)d_in[5];   // [H,1]
    float* out = (float*)d_out;

    // Phase 1: x_proj into the hidden_seq region of d_out
    dim3 g1(RH / BN, RS);   // (8, 2048)
    rnn_xproj<<<g1, 256>>>(inputs, w_ih, b_ih, b_hh, out);

    // Phase 2: recurrence (16 clusters x 8 CTAs)
    cudaFuncSetAttribute(rnn_recur, cudaFuncAttributeMaxDynamicSharedMemorySize, SMEM_BYTES);
    int has_tail = (out_size > RS * RB * RH) ? 1 : 0;
    rnn_recur<<<128, 512, SMEM_BYTES>>>(w_hh, state, out, has_tail);
}

// round 2
// speedup vs baseline: 1.7777x; 1.7777x over previous
#include <cuda_runtime.h>
#include <cstdint>
#include <cstddef>

// Problem constants
#define RH 512
#define RB 64
#define RS 2048
#define RI 512

// ---------------------------------------------------------------------------
// f32x2 packed helpers (sm_100a)
// ---------------------------------------------------------------------------
__device__ __forceinline__ void ffma2(unsigned long long &d,
                                      unsigned long long a,
                                      unsigned long long b) {
    asm("fma.rn.f32x2 %0, %1, %2, %0;" : "+l"(d) : "l"(a), "l"(b));
}
__device__ __forceinline__ unsigned long long dup2(float x) {
    unsigned long long r;
    asm("mov.b64 %0, {%1, %1};" : "=l"(r) : "f"(x));
    return r;
}
__device__ __forceinline__ float2 unpack2(unsigned long long v) {
    float2 r;
    asm("mov.b64 {%0, %1}, %2;" : "=f"(r.x), "=f"(r.y) : "l"(v));
    return r;
}
__device__ __forceinline__ float lo_plus_hi(unsigned long long v) {
    float2 r = unpack2(v);
    return r.x + r.y;
}

// ---------------------------------------------------------------------------
// Phase 1: x_proj GEMM. out[(s*B+b)*H + h] = inputs[b,s,:]·w_ih[h,:] + bih+bhh
// BM=64 (one s, all b), BN=128, BK=16, 256 threads.
// Thread tile: 4 m x 8 n (n split as two float4 groups 64 apart).
// Inner product via fma.rn.f32x2 (a duplicated, b natural pairs).
// ---------------------------------------------------------------------------
#define BN 128
#define BK 16
#define AS_PITCH 68
#define WS_PITCH 136

__global__ void __launch_bounds__(256)
rnn_xproj(const float* __restrict__ A,    // inputs [B,S,I]
          const float* __restrict__ Wih,  // [H,I]
          const float* __restrict__ bih,
          const float* __restrict__ bhh,
          float* __restrict__ out)
{
    __shared__ float As[BK * AS_PITCH];
    __shared__ float Ws[BK * WS_PITCH];

    const int tid = threadIdx.x;
    const int s  = blockIdx.y;
    const int h0 = blockIdx.x * BN;
    const int r0 = s * RB;

    const int tm0 = (tid >> 4) << 2;       // 0..60 (m)
    const int tn  = (tid & 15) << 2;       // 0..60 (n, plus +64 group)

    const int a_r = tid >> 2;              // 0..63
    const int a_k = (tid & 3) << 2;        // 0,4,8,12

    const float* Arow  = A   + ((size_t)a_r * RS + s) * RI;
    const float* Wrow0 = Wih + (size_t)(h0 + a_r) * RI;
    const float* Wrow1 = Wih + (size_t)(h0 + 64 + a_r) * RI;

    unsigned long long c2[4][4];
    #pragma unroll
    for (int i = 0; i < 4; i++)
        #pragma unroll
        for (int j = 0; j < 4; j++) c2[i][j] = 0ull;

    for (int k0 = 0; k0 < RI; k0 += BK) {
        float4 av = *reinterpret_cast<const float4*>(Arow  + k0 + a_k);
        float4 w0 = *reinterpret_cast<const float4*>(Wrow0 + k0 + a_k);
        float4 w1 = *reinterpret_cast<const float4*>(Wrow1 + k0 + a_k);
        As[(a_k + 0) * AS_PITCH + a_r] = av.x;
        As[(a_k + 1) * AS_PITCH + a_r] = av.y;
        As[(a_k + 2) * AS_PITCH + a_r] = av.z;
        As[(a_k + 3) * AS_PITCH + a_r] = av.w;
        Ws[(a_k + 0) * WS_PITCH + a_r] = w0.x;
        Ws[(a_k + 1) * WS_PITCH + a_r] = w0.y;
        Ws[(a_k + 2) * WS_PITCH + a_r] = w0.z;
        Ws[(a_k + 3) * WS_PITCH + a_r] = w0.w;
        Ws[(a_k + 0) * WS_PITCH + 64 + a_r] = w1.x;
        Ws[(a_k + 1) * WS_PITCH + 64 + a_r] = w1.y;
        Ws[(a_k + 2) * WS_PITCH + 64 + a_r] = w1.z;
        Ws[(a_k + 3) * WS_PITCH + 64 + a_r] = w1.w;
        __syncthreads();
        #pragma unroll
        for (int kk = 0; kk < BK; kk++) {
            float4 a = *reinterpret_cast<const float4*>(&As[kk * AS_PITCH + tm0]);
            ulonglong2 bA = *reinterpret_cast<const ulonglong2*>(&Ws[kk * WS_PITCH + tn]);
            ulonglong2 bB = *reinterpret_cast<const ulonglong2*>(&Ws[kk * WS_PITCH + 64 + tn]);
            unsigned long long am0 = dup2(a.x), am1 = dup2(a.y),
                               am2 = dup2(a.z), am3 = dup2(a.w);
            ffma2(c2[0][0], am0, bA.x); ffma2(c2[0][1], am0, bA.y);
            ffma2(c2[0][2], am0, bB.x); ffma2(c2[0][3], am0, bB.y);
            ffma2(c2[1][0], am1, bA.x); ffma2(c2[1][1], am1, bA.y);
            ffma2(c2[1][2], am1, bB.x); ffma2(c2[1][3], am1, bB.y);
            ffma2(c2[2][0], am2, bA.x); ffma2(c2[2][1], am2, bA.y);
            ffma2(c2[2][2], am2, bB.x); ffma2(c2[2][3], am2, bB.y);
            ffma2(c2[3][0], am3, bA.x); ffma2(c2[3][1], am3, bA.y);
            ffma2(c2[3][2], am3, bB.x); ffma2(c2[3][3], am3, bB.y);
        }
        __syncthreads();
    }

    const int hA = h0 + tn;
    const int hB = h0 + 64 + tn;
    float4 biA, biB;
    {
        float4 b1 = *reinterpret_cast<const float4*>(bih + hA);
        float4 b2 = *reinterpret_cast<const float4*>(bhh + hA);
        biA = make_float4(b1.x + b2.x, b1.y + b2.y, b1.z + b2.z, b1.w + b2.w);
        float4 b3 = *reinterpret_cast<const float4*>(bih + hB);
        float4 b4 = *reinterpret_cast<const float4*>(bhh + hB);
        biB = make_float4(b3.x + b4.x, b3.y + b4.y, b3.z + b4.z, b3.w + b4.w);
    }
    #pragma unroll
    for (int im = 0; im < 4; im++) {
        int r = r0 + tm0 + im;
        float2 uA0 = unpack2(c2[im][0]);
        float2 uA1 = unpack2(c2[im][1]);
        float2 uB0 = unpack2(c2[im][2]);
        float2 uB1 = unpack2(c2[im][3]);
        float4 oA = make_float4(uA0.x + biA.x, uA0.y + biA.y, uA1.x + biA.z, uA1.y + biA.w);
        float4 oB = make_float4(uB0.x + biB.x, uB0.y + biB.y, uB1.x + biB.z, uB1.y + biB.w);
        *reinterpret_cast<float4*>(&out[(size_t)r * RH + hA]) = oA;
        *reinterpret_cast<float4*>(&out[(size_t)r * RH + hB]) = oB;
    }
}

// ---------------------------------------------------------------------------
// Phase 2: recurrence. 16 clusters x 8 CTAs, 512 threads/CTA.
// W_hh slice (64 rows x 512 cols per CTA) is REGISTER-resident: each lane
// holds W[j0+j_local, kg*64 .. kg*64+64) as 32 packed f32x2 values.
// h (4 batches) replicated per CTA in SMEM, double-buffered; per step each
// warp computes 4 j x 4 b with k split 8-ways across lane groups, shfl-reduce,
// DSMEM broadcast of new h slice, one cluster barrier per step.
// ---------------------------------------------------------------------------
#define CSZ 8
#define HBUF_F4 544                 // 4 b * 8 kg blocks * 17 float4

__device__ __forceinline__ uint32_t smem_u32(const void* p) {
    return (uint32_t)__cvta_generic_to_shared(p);
}
__device__ __forceinline__ uint32_t mapa_u32(uint32_t addr, uint32_t rank) {
    uint32_t r;
    asm("mapa.shared::cluster.u32 %0, %1, %2;" : "=r"(r) : "r"(addr), "r"(rank));
    return r;
}
__device__ __forceinline__ void st_cluster_f32(uint32_t addr, float v) {
    asm volatile("st.shared::cluster.f32 [%0], %1;" :: "r"(addr), "f"(v) : "memory");
}
__device__ __forceinline__ void cluster_arrive_wait() {
    asm volatile("barrier.cluster.arrive.aligned;" ::: "memory");
    asm volatile("barrier.cluster.wait.aligned;"   ::: "memory");
}

__global__ void __cluster_dims__(CSZ, 1, 1) __launch_bounds__(512, 1)
rnn_recur(const float* __restrict__ w_hh,
          const float* __restrict__ state,
          float* __restrict__ out,
          int has_tail)
{
    __shared__ float4 Hv[2 * HBUF_F4];

    const int tid = threadIdx.x;
    const int w = tid >> 5;
    const int l = tid & 31;
    uint32_t rank;
    asm("mov.u32 %0, %%cluster_ctarank;" : "=r"(rank));
    const int cl = blockIdx.x >> 3;
    const int j0 = (int)rank * 64;
    const int b0 = cl * 4;

    const int jj = l & 3;
    const int kg = l >> 2;                 // k-chunk 0..7 (64 k each)
    const int j_local = (w << 2) + jj;     // 0..63

    // --- W_hh slice into registers: 32 packed f32x2 (64 floats) per lane ---
    unsigned long long wreg[32];
    {
        const ulonglong2* ws = reinterpret_cast<const ulonglong2*>(
            w_hh + ((size_t)(j0 + j_local) << 9) + ((size_t)kg << 6));
        #pragma unroll
        for (int i = 0; i < 16; i++) {
            ulonglong2 v = ws[i];
            wreg[2 * i]     = v.x;
            wreg[2 * i + 1] = v.y;
        }
    }

    // --- initial state into buf0 (padded 17-f4 blocks keyed by (b,kg)) ---
    for (int v = tid; v < 4 * 128; v += 512) {
        int b  = v >> 7;
        int kv = v & 127;
        float4 x = __ldg(reinterpret_cast<const float4*>(state) + ((size_t)(b0 + b) << 7) + kv);
        Hv[((b << 3) + (kv >> 4)) * 17 + (kv & 15)] = x;
    }
    __syncthreads();

    const bool act = (l < 16);
    const int ob = l >> 2;
    const size_t row_stride = (size_t)RB * RH;
    const size_t oidx = (size_t)(b0 + ob) * RH + (size_t)(j0 + j_local);
    const int kglob = j0 + j_local;
    const int slot_f4 = ((ob << 3) + (kglob >> 6)) * 17 + ((kglob >> 2) & 15);
    const uint32_t slot_addr = smem_u32(Hv) + (uint32_t)slot_f4 * 16u
                             + (uint32_t)(kglob & 3) * 4u;
    const uint32_t bufoff = HBUF_F4 * 16u;

    const int offb0 = (kg) * 17;
    const int offb1 = (8 + kg) * 17;
    const int offb2 = (16 + kg) * 17;
    const int offb3 = (24 + kg) * 17;

    float xp_cur = act ? __ldg(out + oidx) : 0.f;

    cluster_arrive_wait();   // all buffers initialized cluster-wide

    int buf = 0;
    for (int s = 0; s < RS; ++s) {
        float xp_next = 0.f;
        if (act && (s + 1 < RS))
            xp_next = __ldg(out + oidx + (size_t)(s + 1) * row_stride);

        const float4* base = Hv + buf * HBUF_F4;
        unsigned long long p0 = 0ull, p1 = 0ull, p2 = 0ull, p3 = 0ull;
        unsigned long long q0 = 0ull, q1 = 0ull, q2 = 0ull, q3 = 0ull;
        #pragma unroll
        for (int i = 0; i < 16; i++) {
            ulonglong2 h0 = *reinterpret_cast<const ulonglong2*>(base + offb0 + i);
            ulonglong2 h1 = *reinterpret_cast<const ulonglong2*>(base + offb1 + i);
            ulonglong2 h2 = *reinterpret_cast<const ulonglong2*>(base + offb2 + i);
            ulonglong2 h3 = *reinterpret_cast<const ulonglong2*>(base + offb3 + i);
            unsigned long long w0 = wreg[2 * i], w1 = wreg[2 * i + 1];
            ffma2(p0, w0, h0.x); ffma2(q0, w1, h0.y);
            ffma2(p1, w0, h1.x); ffma2(q1, w1, h1.y);
            ffma2(p2, w0, h2.x); ffma2(q2, w1, h2.y);
            ffma2(p3, w0, h3.x); ffma2(q3, w1, h3.y);
        }
        float a0 = lo_plus_hi(p0) + lo_plus_hi(q0);
        float a1 = lo_plus_hi(p1) + lo_plus_hi(q1);
        float a2 = lo_plus_hi(p2) + lo_plus_hi(q2);
        float a3 = lo_plus_hi(p3) + lo_plus_hi(q3);
        #pragma unroll
        for (int off = 4; off < 32; off <<= 1) {
            a0 += __shfl_xor_sync(0xffffffffu, a0, off);
            a1 += __shfl_xor_sync(0xffffffffu, a1, off);
            a2 += __shfl_xor_sync(0xffffffffu, a2, off);
            a3 += __shfl_xor_sync(0xffffffffu, a3, off);
        }

        if (act) {
            float acc = (ob == 0) ? a0 : ((ob == 1) ? a1 : ((ob == 2) ? a2 : a3));
            float y = tanhf(xp_cur + acc);
            out[oidx + (size_t)s * row_stride] = y;
            if (has_tail && (s == RS - 1))
                out[(size_t)RS * RB * RH + (size_t)kglob * RB + (size_t)(b0 + ob)] = y;
            uint32_t woff = buf ? 0u : bufoff;
            uint32_t dst = slot_addr + woff;
            #pragma unroll
            for (int c = 0; c < CSZ; c++)
                st_cluster_f32(mapa_u32(dst, (uint32_t)c), y);
        }

        cluster_arrive_wait();

        buf ^= 1;
        xp_cur = xp_next;
    }
}

// ---------------------------------------------------------------------------
// Launch
// ---------------------------------------------------------------------------
extern "C" void kernel_launch(void* const* d_in, const int* in_sizes, int n_in,
                              void* d_out, int out_size)
{
    const float* inputs = (const float*)d_in[0];
    const float* state  = (const float*)d_in[1];
    const float* w_ih   = (const float*)d_in[2];
    const float* b_ih   = (const float*)d_in[3];
    const float* w_hh   = (const float*)d_in[4];
    const float* b_hh   = (const float*)d_in[5];
    float* out = (float*)d_out;

    dim3 g1(RH / BN, RS);   // (4, 2048)
    rnn_xproj<<<g1, 256>>>(inputs, w_ih, b_ih, b_hh, out);

    int has_tail = (out_size > RS * RB * RH) ? 1 : 0;
    rnn_recur<<<128, 512>>>(w_hh, state, out, has_tail);
}

// round 3
// speedup vs baseline: 1.8026x; 1.0140x over previous
#include <cuda_runtime.h>
#include <cstdint>
#include <cstddef>

// Problem constants
#define RH 512
#define RB 64
#define RS 2048
#define RI 512

// ---------------------------------------------------------------------------
// f32x2 packed helpers (sm_100a)
// ---------------------------------------------------------------------------
__device__ __forceinline__ void ffma2(unsigned long long &d,
                                      unsigned long long a,
                                      unsigned long long b) {
    asm("fma.rn.f32x2 %0, %1, %2, %0;" : "+l"(d) : "l"(a), "l"(b));
}
__device__ __forceinline__ unsigned long long dup2(float x) {
    unsigned long long r;
    asm("mov.b64 %0, {%1, %1};" : "=l"(r) : "f"(x));
    return r;
}
__device__ __forceinline__ float2 unpack2(unsigned long long v) {
    float2 r;
    asm("mov.b64 {%0, %1}, %2;" : "=f"(r.x), "=f"(r.y) : "l"(v));
    return r;
}
__device__ __forceinline__ float lo_plus_hi(unsigned long long v) {
    float2 r = unpack2(v);
    return r.x + r.y;
}

// ---------------------------------------------------------------------------
// Phase 1: x_proj GEMM (unchanged from R2; ~74% of f32x2 issue peak)
// ---------------------------------------------------------------------------
#define BN 128
#define BK 16
#define AS_PITCH 68
#define WS_PITCH 136

__global__ void __launch_bounds__(256)
rnn_xproj(const float* __restrict__ A,
          const float* __restrict__ Wih,
          const float* __restrict__ bih,
          const float* __restrict__ bhh,
          float* __restrict__ out)
{
    __shared__ float As[BK * AS_PITCH];
    __shared__ float Ws[BK * WS_PITCH];

    const int tid = threadIdx.x;
    const int s  = blockIdx.y;
    const int h0 = blockIdx.x * BN;
    const int r0 = s * RB;

    const int tm0 = (tid >> 4) << 2;
    const int tn  = (tid & 15) << 2;

    const int a_r = tid >> 2;
    const int a_k = (tid & 3) << 2;

    const float* Arow  = A   + ((size_t)a_r * RS + s) * RI;
    const float* Wrow0 = Wih + (size_t)(h0 + a_r) * RI;
    const float* Wrow1 = Wih + (size_t)(h0 + 64 + a_r) * RI;

    unsigned long long c2[4][4];
    #pragma unroll
    for (int i = 0; i < 4; i++)
        #pragma unroll
        for (int j = 0; j < 4; j++) c2[i][j] = 0ull;

    for (int k0 = 0; k0 < RI; k0 += BK) {
        float4 av = *reinterpret_cast<const float4*>(Arow  + k0 + a_k);
        float4 w0 = *reinterpret_cast<const float4*>(Wrow0 + k0 + a_k);
        float4 w1 = *reinterpret_cast<const float4*>(Wrow1 + k0 + a_k);
        As[(a_k + 0) * AS_PITCH + a_r] = av.x;
        As[(a_k + 1) * AS_PITCH + a_r] = av.y;
        As[(a_k + 2) * AS_PITCH + a_r] = av.z;
        As[(a_k + 3) * AS_PITCH + a_r] = av.w;
        Ws[(a_k + 0) * WS_PITCH + a_r] = w0.x;
        Ws[(a_k + 1) * WS_PITCH + a_r] = w0.y;
        Ws[(a_k + 2) * WS_PITCH + a_r] = w0.z;
        Ws[(a_k + 3) * WS_PITCH + a_r] = w0.w;
        Ws[(a_k + 0) * WS_PITCH + 64 + a_r] = w1.x;
        Ws[(a_k + 1) * WS_PITCH + 64 + a_r] = w1.y;
        Ws[(a_k + 2) * WS_PITCH + 64 + a_r] = w1.z;
        Ws[(a_k + 3) * WS_PITCH + 64 + a_r] = w1.w;
        __syncthreads();
        #pragma unroll
        for (int kk = 0; kk < BK; kk++) {
            float4 a = *reinterpret_cast<const float4*>(&As[kk * AS_PITCH + tm0]);
            ulonglong2 bA = *reinterpret_cast<const ulonglong2*>(&Ws[kk * WS_PITCH + tn]);
            ulonglong2 bB = *reinterpret_cast<const ulonglong2*>(&Ws[kk * WS_PITCH + 64 + tn]);
            unsigned long long am0 = dup2(a.x), am1 = dup2(a.y),
                               am2 = dup2(a.z), am3 = dup2(a.w);
            ffma2(c2[0][0], am0, bA.x); ffma2(c2[0][1], am0, bA.y);
            ffma2(c2[0][2], am0, bB.x); ffma2(c2[0][3], am0, bB.y);
            ffma2(c2[1][0], am1, bA.x); ffma2(c2[1][1], am1, bA.y);
            ffma2(c2[1][2], am1, bB.x); ffma2(c2[1][3], am1, bB.y);
            ffma2(c2[2][0], am2, bA.x); ffma2(c2[2][1], am2, bA.y);
            ffma2(c2[2][2], am2, bB.x); ffma2(c2[2][3], am2, bB.y);
            ffma2(c2[3][0], am3, bA.x); ffma2(c2[3][1], am3, bA.y);
            ffma2(c2[3][2], am3, bB.x); ffma2(c2[3][3], am3, bB.y);
        }
        __syncthreads();
    }

    const int hA = h0 + tn;
    const int hB = h0 + 64 + tn;
    float4 biA, biB;
    {
        float4 b1 = *reinterpret_cast<const float4*>(bih + hA);
        float4 b2 = *reinterpret_cast<const float4*>(bhh + hA);
        biA = make_float4(b1.x + b2.x, b1.y + b2.y, b1.z + b2.z, b1.w + b2.w);
        float4 b3 = *reinterpret_cast<const float4*>(bih + hB);
        float4 b4 = *reinterpret_cast<const float4*>(bhh + hB);
        biB = make_float4(b3.x + b4.x, b3.y + b4.y, b3.z + b4.z, b3.w + b4.w);
    }
    #pragma unroll
    for (int im = 0; im < 4; im++) {
        int r = r0 + tm0 + im;
        float2 uA0 = unpack2(c2[im][0]);
        float2 uA1 = unpack2(c2[im][1]);
        float2 uB0 = unpack2(c2[im][2]);
        float2 uB1 = unpack2(c2[im][3]);
        float4 oA = make_float4(uA0.x + biA.x, uA0.y + biA.y, uA1.x + biA.z, uA1.y + biA.w);
        float4 oB = make_float4(uB0.x + biB.x, uB0.y + biB.y, uB1.x + biB.z, uB1.y + biB.w);
        *reinterpret_cast<float4*>(&out[(size_t)r * RH + hA]) = oA;
        *reinterpret_cast<float4*>(&out[(size_t)r * RH + hB]) = oB;
    }
}

// ---------------------------------------------------------------------------
// Phase 2: recurrence. 16 clusters x 8 CTAs, 512 threads/CTA.
// W_hh register-resident (64 f32/lane). Per step:
//   compute -> stage y locally -> __syncthreads -> cooperative float4
//   broadcast (1 store/thread to a fixed remote) -> cluster barrier.
// ---------------------------------------------------------------------------
#define CSZ 8
#define HBUF_F4 544                 // 4 b * 8 kg blocks * 17 float4
#define STAGE_F4 68                 // 4 ob * 17 float4 (68-float pitch)

__device__ __forceinline__ uint32_t smem_u32(const void* p) {
    return (uint32_t)__cvta_generic_to_shared(p);
}
__device__ __forceinline__ uint32_t mapa_u32(uint32_t addr, uint32_t rank) {
    uint32_t r;
    asm("mapa.shared::cluster.u32 %0, %1, %2;" : "=r"(r) : "r"(addr), "r"(rank));
    return r;
}
__device__ __forceinline__ void st_cluster_v4(uint32_t addr, float4 v) {
    asm volatile("st.shared::cluster.v4.f32 [%0], {%1,%2,%3,%4};"
                 :: "r"(addr), "f"(v.x), "f"(v.y), "f"(v.z), "f"(v.w) : "memory");
}
__device__ __forceinline__ void cluster_arrive() {
    asm volatile("barrier.cluster.arrive.aligned;" ::: "memory");
}
__device__ __forceinline__ void cluster_wait() {
    asm volatile("barrier.cluster.wait.aligned;" ::: "memory");
}

__global__ void __cluster_dims__(CSZ, 1, 1) __launch_bounds__(512, 1)
rnn_recur(const float* __restrict__ w_hh,
          const float* __restrict__ state,
          float* __restrict__ out,
          int has_tail)
{
    __shared__ float4 Hv[2 * HBUF_F4];
    __shared__ float4 Stg[STAGE_F4];

    const int tid = threadIdx.x;
    const int w = tid >> 5;
    const int l = tid & 31;
    uint32_t rank;
    asm("mov.u32 %0, %%cluster_ctarank;" : "=r"(rank));
    const int cl = blockIdx.x >> 3;
    const int j0 = (int)rank * 64;
    const int b0 = cl * 4;

    const int jj = l & 3;
    const int kg = l >> 2;
    const int j_local = (w << 2) + jj;

    // --- W_hh slice into registers: 32 packed f32x2 (64 floats) per lane ---
    unsigned long long wreg[32];
    {
        const ulonglong2* ws = reinterpret_cast<const ulonglong2*>(
            w_hh + ((size_t)(j0 + j_local) << 9) + ((size_t)kg << 6));
        #pragma unroll
        for (int i = 0; i < 16; i++) {
            ulonglong2 v = ws[i];
            wreg[2 * i]     = v.x;
            wreg[2 * i + 1] = v.y;
        }
    }

    // --- initial state into buf0 ---
    for (int v = tid; v < 4 * 128; v += 512) {
        int b  = v >> 7;
        int kv = v & 127;
        float4 x = __ldg(reinterpret_cast<const float4*>(state) + ((size_t)(b0 + b) << 7) + kv);
        Hv[((b << 3) + (kv >> 4)) * 17 + (kv & 15)] = x;
    }
    __syncthreads();

    const bool act = (l < 16);
    const int ob = l >> 2;
    const size_t row_stride = (size_t)RB * RH;
    const size_t oidx = (size_t)(b0 + ob) * RH + (size_t)(j0 + j_local);
    const int kglob = j0 + j_local;

    // staging slot for this act lane: Stg floats [ob*68 + j_local]
    float* stg_f = reinterpret_cast<float*>(Stg);
    const int stg_idx = ob * 68 + j_local;

    // broadcast assignment: this thread moves one float4 each step
    const int bc_c   = tid >> 6;           // target CTA rank 0..7
    const int bc_idx = tid & 63;
    const int bc_ob  = bc_idx >> 4;        // 0..3
    const int bc_i   = bc_idx & 15;        // 0..15
    // source in staging
    const int src_f4 = bc_ob * 17 + bc_i;
    // destination slot (buf-relative) in target CTA's Hv
    const uint32_t dst_off = (uint32_t)((((bc_ob << 3) + (int)rank) * 17 + bc_i) * 16);
    const uint32_t remBase = mapa_u32(smem_u32(Hv) + dst_off, (uint32_t)bc_c);
    const uint32_t bufoff = HBUF_F4 * 16u;

    const int offb0 = (kg) * 17;
    const int offb1 = (8 + kg) * 17;
    const int offb2 = (16 + kg) * 17;
    const int offb3 = (24 + kg) * 17;

    float xp_cur = act ? __ldg(out + oidx) : 0.f;

    cluster_arrive(); cluster_wait();   // buffers valid cluster-wide

    int buf = 0;
    for (int s = 0; s < RS; ++s) {
        const float4* base = Hv + buf * HBUF_F4;
        unsigned long long p0 = 0ull, p1 = 0ull, p2 = 0ull, p3 = 0ull;
        unsigned long long q0 = 0ull, q1 = 0ull, q2 = 0ull, q3 = 0ull;
        #pragma unroll
        for (int i = 0; i < 16; i++) {
            ulonglong2 h0 = *reinterpret_cast<const ulonglong2*>(base + offb0 + i);
            ulonglong2 h1 = *reinterpret_cast<const ulonglong2*>(base + offb1 + i);
            ulonglong2 h2 = *reinterpret_cast<const ulonglong2*>(base + offb2 + i);
            ulonglong2 h3 = *reinterpret_cast<const ulonglong2*>(base + offb3 + i);
            unsigned long long w0 = wreg[2 * i], w1 = wreg[2 * i + 1];
            ffma2(p0, w0, h0.x); ffma2(q0, w1, h0.y);
            ffma2(p1, w0, h1.x); ffma2(q1, w1, h1.y);
            ffma2(p2, w0, h2.x); ffma2(q2, w1, h2.y);
            ffma2(p3, w0, h3.x); ffma2(q3, w1, h3.y);
        }
        float a0 = lo_plus_hi(p0) + lo_plus_hi(q0);
        float a1 = lo_plus_hi(p1) + lo_plus_hi(q1);
        float a2 = lo_plus_hi(p2) + lo_plus_hi(q2);
        float a3 = lo_plus_hi(p3) + lo_plus_hi(q3);
        #pragma unroll
        for (int off = 4; off < 32; off <<= 1) {
            a0 += __shfl_xor_sync(0xffffffffu, a0, off);
            a1 += __shfl_xor_sync(0xffffffffu, a1, off);
            a2 += __shfl_xor_sync(0xffffffffu, a2, off);
            a3 += __shfl_xor_sync(0xffffffffu, a3, off);
        }

        if (act) {
            float acc = (ob == 0) ? a0 : ((ob == 1) ? a1 : ((ob == 2) ? a2 : a3));
            float y = tanhf(xp_cur + acc);
            stg_f[stg_idx] = y;
            out[oidx + (size_t)s * row_stride] = y;
            if (has_tail && (s == RS - 1))
                out[(size_t)RS * RB * RH + (size_t)kglob * RB + (size_t)(b0 + ob)] = y;
        }

        __syncthreads();   // staging complete, visible to all warps

        // cooperative broadcast: one float4 per thread into the OTHER buffer
        {
            float4 v = Stg[src_f4];
            uint32_t dst = remBase + (buf ? 0u : bufoff);
            st_cluster_v4(dst, v);
        }

        cluster_arrive();

        // prefetch next xp under the barrier wait
        float xp_next = 0.f;
        if (act && (s + 1 < RS))
            xp_next = __ldg(out + oidx + (size_t)(s + 1) * row_stride);

        cluster_wait();

        buf ^= 1;
        xp_cur = xp_next;
    }
}

// ---------------------------------------------------------------------------
// Launch
// ---------------------------------------------------------------------------
extern "C" void kernel_launch(void* const* d_in, const int* in_sizes, int n_in,
                              void* d_out, int out_size)
{
    const float* inputs = (const float*)d_in[0];
    const float* state  = (const float*)d_in[1];
    const float* w_ih   = (const float*)d_in[2];
    const float* b_ih   = (const float*)d_in[3];
    const float* w_hh   = (const float*)d_in[4];
    const float* b_hh   = (const float*)d_in[5];
    float* out = (float*)d_out;

    dim3 g1(RH / BN, RS);   // (4, 2048)
    rnn_xproj<<<g1, 256>>>(inputs, w_ih, b_ih, b_hh, out);

    int has_tail = (out_size > RS * RB * RH) ? 1 : 0;
    rnn_recur<<<128, 512>>>(w_hh, state, out, has_tail);
}